// round 3
// baseline (speedup 1.0000x reference)
#include <cuda_runtime.h>
#include <cuda_bf16.h>
#include <cstdint>

// Problem constants (fixed by setup_inputs)
#define NB 16      // batch
#define LL 512     // sequence length
#define DD 256     // encoder dim = filter size
#define TT 4096    // WVF_max_length
#define TP 16      // L-positions per conv block
#define DC 16      // d-chunk staged in smem

// Intermediates (no cudaMalloc allowed) — referenced directly from device code,
// never via host-side symbol lookup.
__device__ float g_h1[NB * LL * DD];
__device__ float g_h2[NB * LL * DD];
__device__ int   g_ends[NB * LL];
__device__ int   g_lmap[NB * TT];

// ---------------------------------------------------------------------------
// Fused conv1d(K=3, same pad) + bias + LayerNorm(F) + ReLU
// STAGE 0: src = x (param), dst = g_h1
// STAGE 1: src = g_h1,      dst = g_h2
// One block = 16 consecutive L positions, 256 threads (one per output channel f)
// ---------------------------------------------------------------------------
template<int STAGE>
__global__ void __launch_bounds__(256) conv_ln_relu_kernel(
    const float* __restrict__ x,
    const float* __restrict__ w,
    const float* __restrict__ bias,
    const float* __restrict__ gamma,
    const float* __restrict__ beta)
{
    __shared__ float xs[TP + 2][DD];   // 18 KB: input rows l0-1 .. l0+16
    __shared__ float ws[DC][256];      // 16 KB: weight chunk; reused as h tile
    __shared__ float mu_s[TP];
    __shared__ float rs_s[TP];

    const float* __restrict__ src = (STAGE == 0) ? x : (const float*)g_h1;
    float* __restrict__ dst       = (STAGE == 0) ? g_h1 : g_h2;

    const int blk = blockIdx.x;
    const int n   = blk / (LL / TP);
    const int l0  = (blk % (LL / TP)) * TP;
    const int f   = threadIdx.x;

    // Load input rows (with zero padding at sequence edges)
    #pragma unroll
    for (int r = 0; r < TP + 2; r++) {
        int l = l0 - 1 + r;
        xs[r][f] = (l >= 0 && l < LL) ? src[(n * LL + l) * DD + f] : 0.f;
    }

    float acc[TP];
    {
        float bf = bias[f];
        #pragma unroll
        for (int p = 0; p < TP; p++) acc[p] = bf;
    }

    for (int kk = 0; kk < 3; kk++) {
        const float* wk = w + kk * DD * 256;
        for (int d0 = 0; d0 < DD; d0 += DC) {
            __syncthreads();   // protect ws from previous chunk's readers (and xs on first pass)
            #pragma unroll
            for (int r = 0; r < DC; r++)
                ws[r][f] = wk[(d0 + r) * 256 + f];
            __syncthreads();
            #pragma unroll
            for (int dd = 0; dd < DC; dd += 4) {
                float w0 = ws[dd + 0][f];
                float w1 = ws[dd + 1][f];
                float w2 = ws[dd + 2][f];
                float w3 = ws[dd + 3][f];
                #pragma unroll
                for (int p = 0; p < TP; p++) {
                    const float4 xv = *(const float4*)&xs[p + kk][d0 + dd];
                    acc[p] = fmaf(xv.x, w0, acc[p]);
                    acc[p] = fmaf(xv.y, w1, acc[p]);
                    acc[p] = fmaf(xv.z, w2, acc[p]);
                    acc[p] = fmaf(xv.w, w3, acc[p]);
                }
            }
        }
    }

    // LayerNorm over f (256) per position p. Stage h tile into ws (16x256).
    __syncthreads();
    #pragma unroll
    for (int p = 0; p < TP; p++) ws[p][f] = acc[p];
    __syncthreads();

    {
        const int wid = f >> 5, lane = f & 31;
        #pragma unroll
        for (int rr = 0; rr < 2; rr++) {
            int r = wid * 2 + rr;
            float s = 0.f, s2 = 0.f;
            #pragma unroll
            for (int c0 = 0; c0 < 256; c0 += 32) {
                float v = ws[r][c0 + lane];
                s += v; s2 += v * v;
            }
            #pragma unroll
            for (int o = 16; o; o >>= 1) {
                s  += __shfl_xor_sync(0xFFFFFFFFu, s,  o);
                s2 += __shfl_xor_sync(0xFFFFFFFFu, s2, o);
            }
            if (lane == 0) {
                float mu = s * (1.f / 256.f);
                float var = s2 * (1.f / 256.f) - mu * mu;
                mu_s[r] = mu;
                rs_s[r] = rsqrtf(var + 1e-5f);
            }
        }
    }
    __syncthreads();

    {
        float gg = gamma[f], bb = beta[f];
        #pragma unroll
        for (int p = 0; p < TP; p++) {
            float v = (acc[p] - mu_s[p]) * rs_s[p] * gg + bb;
            dst[(n * LL + l0 + p) * 256 + f] = fmaxf(v, 0.f);
        }
    }
}

// ---------------------------------------------------------------------------
// dpo = relu(h2 @ lin_w + lin_b); dur = int(dpo + 0.5); inclusive scan per row
// One block per n, 512 threads (one per l). Writes g_ends.
// ---------------------------------------------------------------------------
__global__ void __launch_bounds__(512) duration_scan_kernel(
    const float* __restrict__ lin_w,
    const float* __restrict__ lin_b)
{
    const int n = blockIdx.x;
    const int l = threadIdx.x;

    const float4* hp = (const float4*)(g_h2 + (n * LL + l) * DD);
    const float4* wp = (const float4*)lin_w;
    float s = 0.f;
    #pragma unroll 4
    for (int d = 0; d < DD / 4; d++) {
        float4 h4 = hp[d];
        float4 w4 = wp[d];
        s += h4.x * w4.x + h4.y * w4.y + h4.z * w4.z + h4.w * w4.w;
    }
    s += lin_b[0];
    s = fmaxf(s, 0.f);
    int dur = (int)(s + 0.5f);   // ALPHA = 1.0; truncation matches astype(int32)

    __shared__ int sc[LL];
    sc[l] = dur;
    __syncthreads();
    for (int off = 1; off < LL; off <<= 1) {
        int v = (l >= off) ? sc[l - off] : 0;
        __syncthreads();
        sc[l] += v;
        __syncthreads();
    }
    g_ends[n * LL + l] = sc[l];
}

// ---------------------------------------------------------------------------
// For each (n, t) find source index l (or -1 if t >= total duration)
// ---------------------------------------------------------------------------
__global__ void __launch_bounds__(256) map_kernel()
{
    const int n = blockIdx.x;
    __shared__ int se[LL];
    for (int i = threadIdx.x; i < LL; i += blockDim.x) se[i] = g_ends[n * LL + i];
    __syncthreads();
    const int total = se[LL - 1];
    for (int t = threadIdx.x; t < TT; t += blockDim.x) {
        int res = -1;
        if (t < total) {
            int lo = 0, hi = LL - 1;
            while (lo < hi) {
                int mid = (lo + hi) >> 1;
                if (se[mid] > t) hi = mid; else lo = mid + 1;
            }
            res = lo;
        }
        g_lmap[n * TT + t] = res;
    }
}

// ---------------------------------------------------------------------------
// out[n, t, :] = x[n, lmap[n,t], :]  (or zeros). float4 streaming copy.
// ---------------------------------------------------------------------------
__global__ void __launch_bounds__(256) expand_copy_kernel(
    const float* __restrict__ x,
    float* __restrict__ out)
{
    const int idx = blockIdx.x * blockDim.x + threadIdx.x;  // over NB*TT*64 float4
    const int c = idx & 63;
    const int t = (idx >> 6) & (TT - 1);
    const int n = idx >> 18;
    const int l = g_lmap[n * TT + t];
    float4 v = make_float4(0.f, 0.f, 0.f, 0.f);
    if (l >= 0) v = ((const float4*)x)[(n * LL + l) * (DD / 4) + c];
    ((float4*)out)[idx] = v;
}

// ---------------------------------------------------------------------------
// Optional second output: WVF_pos = 1..TT (if the harness concatenated it)
// ---------------------------------------------------------------------------
__global__ void tail_kernel(float* __restrict__ out, int tail)
{
    int i = blockIdx.x * blockDim.x + threadIdx.x;
    if (i < tail) out[NB * TT * DD + i] = (float)((i % TT) + 1);
}

extern "C" void kernel_launch(void* const* d_in, const int* in_sizes, int n_in,
                              void* d_out, int out_size)
{
    const float* x       = (const float*)d_in[0];
    const float* conv1_w = (const float*)d_in[1];
    const float* conv1_b = (const float*)d_in[2];
    const float* ln1_g   = (const float*)d_in[3];
    const float* ln1_b   = (const float*)d_in[4];
    const float* conv2_w = (const float*)d_in[5];
    const float* conv2_b = (const float*)d_in[6];
    const float* ln2_g   = (const float*)d_in[7];
    const float* ln2_b   = (const float*)d_in[8];
    const float* lin_w   = (const float*)d_in[9];
    const float* lin_b   = (const float*)d_in[10];

    float* out = (float*)d_out;

    // Pure kernel launches only — fully graph-capturable, no runtime API calls.
    const int conv_grid = NB * (LL / TP);   // 512
    conv_ln_relu_kernel<0><<<conv_grid, 256>>>(x, conv1_w, conv1_b, ln1_g, ln1_b);
    conv_ln_relu_kernel<1><<<conv_grid, 256>>>(x, conv2_w, conv2_b, ln2_g, ln2_b);
    duration_scan_kernel<<<NB, LL>>>(lin_w, lin_b);
    map_kernel<<<NB, 256>>>();

    const int n_f4 = NB * TT * (DD / 4);    // 4,194,304
    expand_copy_kernel<<<n_f4 / 256, 256>>>(x, out);

    const int main_elems = NB * TT * DD;
    int tail = out_size - main_elems;
    if (tail > 0) {
        tail_kernel<<<(tail + 255) / 256, 256>>>(out, tail);
    }
}

// round 5
// speedup vs baseline: 1.6362x; 1.6362x over previous
#include <cuda_runtime.h>
#include <cuda_bf16.h>
#include <cstdint>

// Problem constants (fixed by setup_inputs)
#define NB 16      // batch
#define LL 512     // sequence length
#define DD 256     // encoder dim = filter size
#define TT 4096    // WVF_max_length
#define TP 16      // L-positions per conv block

// Intermediates (no cudaMalloc allowed) — referenced directly from device code.
__device__ float g_h1[NB * LL * DD];
__device__ float g_h2[NB * LL * DD];
__device__ int   g_lmap[NB * TT];

// ---- packed fp32x2 helpers (sm_100a; ptxas never auto-emits FFMA2) ----
__device__ __forceinline__ void fma2(unsigned long long& acc,
                                     unsigned long long a,
                                     unsigned long long b)
{
    asm("fma.rn.f32x2 %0, %1, %2, %0;" : "+l"(acc) : "l"(a), "l"(b));
}
__device__ __forceinline__ unsigned long long pack2(float a, float b)
{
    unsigned long long r;
    asm("mov.b64 %0, {%1, %2};" : "=l"(r) : "f"(a), "f"(b));
    return r;
}
__device__ __forceinline__ float2 unpack2(unsigned long long v)
{
    float2 r;
    asm("mov.b64 {%0, %1}, %2;" : "=f"(r.x), "=f"(r.y) : "l"(v));
    return r;
}

// ---------------------------------------------------------------------------
// Fused conv1d(K=3, same pad) + bias + LayerNorm(F) + ReLU
// STAGE 0: src = x (param), dst = g_h1;  STAGE 1: src = g_h1, dst = g_h2
// One block = 16 consecutive L positions, 256 threads (one per output chan f).
// Weights are per-thread private (fixed f) -> loaded straight from L2 via LDG,
// no smem staging, no barriers in the mainloop.
// ---------------------------------------------------------------------------
template<int STAGE>
__global__ void __launch_bounds__(256) conv_ln_relu_kernel(
    const float* __restrict__ x,
    const float* __restrict__ w,
    const float* __restrict__ bias,
    const float* __restrict__ gamma,
    const float* __restrict__ beta)
{
    __shared__ float xs[TP + 2][DD];   // 18 KB: input rows l0-1 .. l0+16
    __shared__ float hs[TP][DD];       // 16 KB: conv result tile for LN
    __shared__ float mu_s[TP];
    __shared__ float rs_s[TP];

    const float* __restrict__ src = (STAGE == 0) ? x : (const float*)g_h1;
    float* __restrict__ dst       = (STAGE == 0) ? g_h1 : g_h2;

    const int blk = blockIdx.x;
    const int n   = blk / (LL / TP);
    const int l0  = (blk % (LL / TP)) * TP;
    const int f   = threadIdx.x;

    // Load input rows (zero padding at sequence edges)
    #pragma unroll
    for (int r = 0; r < TP + 2; r++) {
        int l = l0 - 1 + r;
        xs[r][f] = (l >= 0 && l < LL) ? src[(n * LL + l) * DD + f] : 0.f;
    }
    __syncthreads();

    // acc2[p] holds (sum over even d, sum over odd d) packed as fp32x2
    unsigned long long acc2[TP];
    #pragma unroll
    for (int p = 0; p < TP; p++) acc2[p] = 0ull;

    // Mainloop: d in steps of 4. Per step: 12 coalesced LDG.32 (weights,
    // L2-resident), 6 mov.b64 packs, 18 LDS.128 (broadcast), 96 FFMA2.
    #pragma unroll 2
    for (int d = 0; d < DD; d += 4) {
        unsigned long long wp01[3], wp23[3];
        #pragma unroll
        for (int kk = 0; kk < 3; kk++) {
            const float* wk = w + kk * (DD * 256) + d * 256 + f;
            float w0 = wk[0];
            float w1 = wk[256];
            float w2 = wk[512];
            float w3 = wk[768];
            wp01[kk] = pack2(w0, w1);
            wp23[kk] = pack2(w2, w3);
        }
        #pragma unroll
        for (int r = 0; r < TP + 2; r++) {
            // one LDS.128 -> two aligned b64 operands, no packing movs
            const ulonglong2 xv = *(const ulonglong2*)&xs[r][d];
            #pragma unroll
            for (int kk = 0; kk < 3; kk++) {
                const int p = r - kk;      // output position using row r at tap kk
                if (p >= 0 && p < TP) {    // compile-time after unroll
                    fma2(acc2[p], xv.x, wp01[kk]);
                    fma2(acc2[p], xv.y, wp23[kk]);
                }
            }
        }
    }

    // Horizontal combine + bias; stage into hs for LayerNorm
    float acc[TP];
    {
        const float bf = bias[f];
        #pragma unroll
        for (int p = 0; p < TP; p++) {
            float2 v = unpack2(acc2[p]);
            acc[p] = v.x + v.y + bf;
            hs[p][f] = acc[p];
        }
    }
    __syncthreads();

    // LayerNorm over f (256) per position p: warp-parallel reductions
    {
        const int wid = f >> 5, lane = f & 31;
        #pragma unroll
        for (int rr = 0; rr < 2; rr++) {
            int r = wid * 2 + rr;
            float s = 0.f, s2 = 0.f;
            #pragma unroll
            for (int c0 = 0; c0 < 256; c0 += 32) {
                float v = hs[r][c0 + lane];
                s += v; s2 += v * v;
            }
            #pragma unroll
            for (int o = 16; o; o >>= 1) {
                s  += __shfl_xor_sync(0xFFFFFFFFu, s,  o);
                s2 += __shfl_xor_sync(0xFFFFFFFFu, s2, o);
            }
            if (lane == 0) {
                float mu = s * (1.f / 256.f);
                float var = s2 * (1.f / 256.f) - mu * mu;
                mu_s[r] = mu;
                rs_s[r] = rsqrtf(var + 1e-5f);
            }
        }
    }
    __syncthreads();

    {
        const float gg = gamma[f], bb = beta[f];
        #pragma unroll
        for (int p = 0; p < TP; p++) {
            float v = (acc[p] - mu_s[p]) * rs_s[p] * gg + bb;
            dst[(n * LL + l0 + p) * 256 + f] = fmaxf(v, 0.f);
        }
    }
}

// ---------------------------------------------------------------------------
// Fused: dpo = relu(h2 @ lin_w + lin_b); dur = int(dpo+0.5); inclusive scan;
// then t -> l binary-search map, all in one block per n (512 threads).
// ---------------------------------------------------------------------------
__global__ void __launch_bounds__(512) duration_map_kernel(
    const float* __restrict__ lin_w,
    const float* __restrict__ lin_b)
{
    const int n = blockIdx.x;
    const int l = threadIdx.x;

    const float4* hp = (const float4*)(g_h2 + (n * LL + l) * DD);
    const float4* wp = (const float4*)lin_w;
    float s = 0.f;
    #pragma unroll 4
    for (int d = 0; d < DD / 4; d++) {
        float4 h4 = hp[d];
        float4 w4 = wp[d];
        s += h4.x * w4.x + h4.y * w4.y + h4.z * w4.z + h4.w * w4.w;
    }
    s += lin_b[0];
    s = fmaxf(s, 0.f);
    int dur = (int)(s + 0.5f);   // ALPHA = 1.0; truncation matches astype(int32)

    // Hillis-Steele inclusive scan in smem
    __shared__ int sc[LL];
    sc[l] = dur;
    __syncthreads();
    for (int off = 1; off < LL; off <<= 1) {
        int v = (l >= off) ? sc[l - off] : 0;
        __syncthreads();
        sc[l] += v;
        __syncthreads();
    }

    // Map: for each t, find l with starts <= t < ends via binary search
    const int total = sc[LL - 1];
    for (int t = l; t < TT; t += LL) {
        int res = -1;
        if (t < total) {
            int lo = 0, hi = LL - 1;
            while (lo < hi) {
                int mid = (lo + hi) >> 1;
                if (sc[mid] > t) hi = mid; else lo = mid + 1;
            }
            res = lo;
        }
        g_lmap[n * TT + t] = res;
    }
}

// ---------------------------------------------------------------------------
// out[n, t, :] = x[n, lmap[n,t], :]  (or zeros). float4 streaming copy.
// ---------------------------------------------------------------------------
__global__ void __launch_bounds__(256) expand_copy_kernel(
    const float* __restrict__ x,
    float* __restrict__ out)
{
    const int idx = blockIdx.x * blockDim.x + threadIdx.x;  // over NB*TT*64 float4
    const int c = idx & 63;
    const int t = (idx >> 6) & (TT - 1);
    const int n = idx >> 18;
    const int l = g_lmap[n * TT + t];
    float4 v = make_float4(0.f, 0.f, 0.f, 0.f);
    if (l >= 0) v = ((const float4*)x)[(n * LL + l) * (DD / 4) + c];
    ((float4*)out)[idx] = v;
}

// ---------------------------------------------------------------------------
// Optional second output: WVF_pos = 1..TT (if the harness concatenated it)
// ---------------------------------------------------------------------------
__global__ void tail_kernel(float* __restrict__ out, int tail)
{
    int i = blockIdx.x * blockDim.x + threadIdx.x;
    if (i < tail) out[NB * TT * DD + i] = (float)((i % TT) + 1);
}

extern "C" void kernel_launch(void* const* d_in, const int* in_sizes, int n_in,
                              void* d_out, int out_size)
{
    const float* x       = (const float*)d_in[0];
    const float* conv1_w = (const float*)d_in[1];
    const float* conv1_b = (const float*)d_in[2];
    const float* ln1_g   = (const float*)d_in[3];
    const float* ln1_b   = (const float*)d_in[4];
    const float* conv2_w = (const float*)d_in[5];
    const float* conv2_b = (const float*)d_in[6];
    const float* ln2_g   = (const float*)d_in[7];
    const float* ln2_b   = (const float*)d_in[8];
    const float* lin_w   = (const float*)d_in[9];
    const float* lin_b   = (const float*)d_in[10];

    float* out = (float*)d_out;

    // Pure kernel launches only — fully graph-capturable.
    const int conv_grid = NB * (LL / TP);   // 512
    conv_ln_relu_kernel<0><<<conv_grid, 256>>>(x, conv1_w, conv1_b, ln1_g, ln1_b);
    conv_ln_relu_kernel<1><<<conv_grid, 256>>>(x, conv2_w, conv2_b, ln2_g, ln2_b);
    duration_map_kernel<<<NB, LL>>>(lin_w, lin_b);

    const int n_f4 = NB * TT * (DD / 4);    // 4,194,304
    expand_copy_kernel<<<n_f4 / 256, 256>>>(x, out);

    const int main_elems = NB * TT * DD;
    int tail = out_size - main_elems;
    if (tail > 0) {
        tail_kernel<<<(tail + 255) / 256, 256>>>(out, tail);
    }
}